// round 16
// baseline (speedup 1.0000x reference)
#include <cuda_runtime.h>
#include <cuda_bf16.h>
#include <cuda_fp16.h>
#include <math_constants.h>
#include <cstdint>

#define B_  8
#define N_  1024
#define C_  768
#define H_  12
#define D_  64
#define SCALE_ 0.125f

// Scratch (device globals: no allocation allowed). Inter-kernel tensors are
// bf16 hi/lo plane pairs (hi = rn(x), lo = rn(x - hi)).
__device__ uint16_t g_xh[(size_t)B_ * N_ * C_],      g_xl[(size_t)B_ * N_ * C_];
__device__ uint16_t g_wqh[(size_t)3 * C_ * C_],      g_wql[(size_t)3 * C_ * C_];
__device__ uint16_t g_wph[(size_t)C_ * C_],          g_wpl[(size_t)C_ * C_];
__device__ uint16_t g_qkvh[(size_t)B_ * N_ * 3 * C_], g_qkvl[(size_t)B_ * N_ * 3 * C_];
__device__ uint16_t g_ah[(size_t)B_ * N_ * C_],      g_al[(size_t)B_ * N_ * C_];
__device__ uint16_t g_p16[(size_t)B_ * H_ * N_ * N_];   // unnormalized probs, fp16
__device__ float    g_rsum[(size_t)B_ * H_ * N_];

// Feature gate: tcgen05 only exists in the sm_103a/sm_100a-specific cubin.
#if defined(__CUDA_ARCH_FEAT_SM103_ALL) || defined(__CUDA_ARCH_FEAT_SM100_ALL)
#define HAS_TCGEN05 1
#else
#define HAS_TCGEN05 0
#endif

// ===========================================================================
// prep: fp32 -> bf16 hi/lo planes. 8 elems per thread.
// ===========================================================================
__global__ __launch_bounds__(256) void prep_kernel(
    const float* __restrict__ src, uint16_t* __restrict__ hi,
    uint16_t* __restrict__ lo, int n8)
{
    int i = blockIdx.x * blockDim.x + threadIdx.x;
    if (i >= n8) return;
    float v[8];
    *(float4*)(v)     = ((const float4*)src)[2 * i];
    *(float4*)(v + 4) = ((const float4*)src)[2 * i + 1];
    uint16_t hv[8], lv[8];
#pragma unroll
    for (int j = 0; j < 8; ++j) {
        __nv_bfloat16 h = __float2bfloat16_rn(v[j]);
        hv[j] = *(uint16_t*)&h;
        __nv_bfloat16 l = __float2bfloat16_rn(v[j] - __bfloat162float(h));
        lv[j] = *(uint16_t*)&l;
    }
    ((uint4*)hi)[i] = *(uint4*)hv;
    ((uint4*)lo)[i] = *(uint4*)lv;
}

#if HAS_TCGEN05
// ===========================================================================
// PTX helpers (verified encodings only)
// ===========================================================================
__device__ __forceinline__ uint32_t smem_u32(const void* p) {
    uint32_t a;
    asm("{ .reg .u64 t; cvta.to.shared.u64 t, %1; cvt.u32.u64 %0, t; }"
        : "=r"(a) : "l"(p));
    return a;
}
__device__ __forceinline__ uint32_t elect_one() {
    uint32_t pred;
    asm volatile("{\n\t.reg .pred p;\n\telect.sync _|p, 0xFFFFFFFF;\n\t"
                 "selp.b32 %0, 1, 0, p;\n\t}" : "=r"(pred));
    return pred;
}
#define TC_ALLOC(sm_addr, n) \
    asm volatile("tcgen05.alloc.cta_group::1.sync.aligned.shared::cta.b32 [%0], %1;" \
                 :: "r"(sm_addr), "r"((uint32_t)(n)) : "memory")
#define TC_DEALLOC(tm, n) \
    asm volatile("tcgen05.dealloc.cta_group::1.sync.aligned.b32 %0, %1;" \
                 :: "r"(tm), "r"((uint32_t)(n)))
#define TC_RELINQ() \
    asm volatile("tcgen05.relinquish_alloc_permit.cta_group::1.sync.aligned;")
#define TC_COMMIT(mbar) \
    asm volatile("tcgen05.commit.cta_group::1.mbarrier::arrive::one.shared::cluster.b64 [%0];" \
                 :: "r"(mbar) : "memory")
#define TC_FENCE_AFTER()  asm volatile("tcgen05.fence::after_thread_sync;" ::: "memory")
#define TC_FENCE_BEFORE() asm volatile("tcgen05.fence::before_thread_sync;" ::: "memory")
#define TC_WAIT_LD() asm volatile("tcgen05.wait::ld.sync.aligned;" ::: "memory")
#define MBAR_INIT(a, c) \
    asm volatile("mbarrier.init.shared.b64 [%0], %1;" :: "r"(a), "r"((uint32_t)(c)) : "memory")
#define MBAR_WAIT(a, ph) do {                                                   \
    uint32_t _m = (a), _p = (ph), _d;                                           \
    asm volatile("{\n\t.reg .pred p;\n\t"                                       \
        "mbarrier.try_wait.parity.acquire.cta.shared::cta.b64 p, [%1], %2;\n\t" \
        "selp.b32 %0, 1, 0, p;\n\t}" : "=r"(_d) : "r"(_m), "r"(_p) : "memory"); \
    if (!_d) {                                                                   \
        asm volatile("{\n\t.reg .pred P1;\n\t"                                   \
            "W%=:\n\t"                                                           \
            "mbarrier.try_wait.parity.acquire.cta.shared::cta.b64 P1, [%0], %1, 0x989680;\n\t" \
            "@P1 bra.uni D%=;\n\t"                                               \
            "bra.uni W%=;\n\t"                                                   \
            "D%=:\n\t}" :: "r"(_m), "r"(_p) : "memory");                         \
    } } while (0)
#define TC_LD_X32(r, tm) \
    asm volatile("tcgen05.ld.sync.aligned.32x32b.x32.b32 " \
        "{%0, %1, %2, %3, %4, %5, %6, %7, %8, %9, %10, %11, %12, %13, %14, %15, " \
        " %16, %17, %18, %19, %20, %21, %22, %23, %24, %25, %26, %27, %28, %29, %30, %31}, [%32];" \
        : "=r"((r)[0]),  "=r"((r)[1]),  "=r"((r)[2]),  "=r"((r)[3]),  \
          "=r"((r)[4]),  "=r"((r)[5]),  "=r"((r)[6]),  "=r"((r)[7]),  \
          "=r"((r)[8]),  "=r"((r)[9]),  "=r"((r)[10]), "=r"((r)[11]), \
          "=r"((r)[12]), "=r"((r)[13]), "=r"((r)[14]), "=r"((r)[15]), \
          "=r"((r)[16]), "=r"((r)[17]), "=r"((r)[18]), "=r"((r)[19]), \
          "=r"((r)[20]), "=r"((r)[21]), "=r"((r)[22]), "=r"((r)[23]), \
          "=r"((r)[24]), "=r"((r)[25]), "=r"((r)[26]), "=r"((r)[27]), \
          "=r"((r)[28]), "=r"((r)[29]), "=r"((r)[30]), "=r"((r)[31]) \
        : "r"(tm))

static constexpr uint64_t DESC_SW128 =
    (uint64_t(2) << 61) | (uint64_t(1) << 46) | (uint64_t(64) << 32) | (uint64_t(1) << 16);
__device__ __forceinline__ uint64_t mk_desc(uint32_t addr) {
    return DESC_SW128 | ((uint64_t)(addr >> 4) & 0x3FFF);
}
__device__ __forceinline__ uint32_t sw128(uint32_t off) {
    return off ^ ((off >> 3) & 0x70);
}
// cvt2(a,b): lo half = a, hi half = b
__device__ __forceinline__ uint32_t cvt2(float a, float b) {
    uint32_t d;
    asm("cvt.rn.bf16x2.f32 %0, %1, %2;" : "=r"(d) : "f"(b), "f"(a));
    return d;
}
// SS-mode bf16 MMA
__device__ __forceinline__ void mma_f16_ss(uint32_t d, uint64_t ad, uint64_t bd,
                                           uint32_t idesc, uint32_t en) {
    asm volatile(
        "{\n\t.reg .pred p;\n\t"
        "setp.ne.u32 p, %5, 0;\n\t"
        "tcgen05.mma.cta_group::1.kind::f16 [%0], %1, %2, %3, {%4, %4, %4, %4}, p;\n\t}"
        :: "r"(d), "l"(ad), "l"(bd), "r"(idesc), "r"(0u), "r"(en) : "memory");
}

static constexpr uint32_t IDESC_128 =
    (1u << 4) | (1u << 7) | (1u << 10) | (16u << 17) | (8u << 24);   // M=128,N=128
static constexpr uint32_t IDESC_N64 =
    (1u << 4) | (1u << 7) | (1u << 10) | (8u << 17) | (8u << 24);    // M=128,N=64
#endif  // HAS_TCGEN05

// ===========================================================================
// GEMM on bf16 planes, single-buffered, 3 CTAs/SM (regs capped at 84).
// MODE 0 (qkv): +scale_emb on cols [768,1536), writes hi/lo planes.
// MODE 1 (proj): +bias, writes fp32.
// ===========================================================================
template <int MODE>
__global__ __launch_bounds__(256, 3) void mma_gemm(
    const uint16_t* __restrict__ Ah, const uint16_t* __restrict__ Al,
    const uint16_t* __restrict__ Wh, const uint16_t* __restrict__ Wl,
    float* __restrict__ Cf, uint16_t* __restrict__ Ch, uint16_t* __restrict__ Cl,
    int Nn, int K, const float* __restrict__ extra)
{
#if HAS_TCGEN05
    extern __shared__ char smc[];
    const uint32_t smem_base = smem_u32(smc);
    const uint32_t TMP = 0, MB = 8;
    const uint32_t BUF = 1024;   // AHI +0, ALO +16K, WHI +32K, WLO +48K

    const int tid = threadIdx.x;
    const int wid = tid >> 5;
    const int m0 = blockIdx.y * 128;
    const int n0 = blockIdx.x * 128;

    if (wid == 0) {
        TC_ALLOC(smem_base + TMP, 128);
        TC_RELINQ();
    }
    if (tid == 0) MBAR_INIT(smem_base + MB, 1);
    __syncthreads();
    uint32_t tmem;
    asm volatile("ld.shared.b32 %0, [%1];" : "=r"(tmem) : "r"(smem_base + TMP));

    const uint64_t dAhi = mk_desc(smem_base + BUF);
    const uint64_t dAlo = mk_desc(smem_base + BUF + 16384);
    const uint64_t dWhi = mk_desc(smem_base + BUF + 32768);
    const uint64_t dWlo = mk_desc(smem_base + BUF + 49152);

    const int nch = K / 64;
    for (int ch = 0; ch < nch; ++ch) {
        const int kt = ch * 64;
#pragma unroll
        for (int it = 0; it < 4; ++it) {
            int task = tid + it * 256;
            int r = task >> 3, g = task & 7;
            uint32_t dst = sw128((uint32_t)(r * 128 + g * 16));
            size_t aoff = (size_t)(m0 + r) * K + kt + g * 8;
            size_t woff = (size_t)(n0 + r) * K + kt + g * 8;
            *(uint4*)(smc + BUF + dst)         = *(const uint4*)(Ah + aoff);
            *(uint4*)(smc + BUF + 16384 + dst) = *(const uint4*)(Al + aoff);
            *(uint4*)(smc + BUF + 32768 + dst) = *(const uint4*)(Wh + woff);
            *(uint4*)(smc + BUF + 49152 + dst) = *(const uint4*)(Wl + woff);
        }
        __syncthreads();

        if (wid == 0) {
            asm volatile("fence.proxy.async.shared::cta;" ::: "memory");
            if (elect_one()) {
#pragma unroll
                for (int ks = 0; ks < 4; ++ks) {
                    uint64_t o = (uint64_t)(ks * 2);
                    mma_f16_ss(tmem, dAhi + o, dWhi + o, IDESC_128,
                               (uint32_t)((ch | ks) != 0));
                    mma_f16_ss(tmem, dAhi + o, dWlo + o, IDESC_128, 1u);
                    mma_f16_ss(tmem, dAlo + o, dWhi + o, IDESC_128, 1u);
                }
                TC_COMMIT(smem_base + MB);
            }
        }
        MBAR_WAIT(smem_base + MB, (uint32_t)(ch & 1));
    }
    TC_FENCE_AFTER();

    const int lane = tid & 31;
    const int sub = wid & 3;
    const int cb = (wid >> 2) * 64;
    const int row = m0 + sub * 32 + lane;

#pragma unroll
    for (int c = 0; c < 2; ++c) {
        uint32_t dr[32];
        TC_LD_X32(dr, tmem + cb + c * 32);
        TC_WAIT_LD();
        float v[32];
#pragma unroll
        for (int j = 0; j < 32; ++j) {
            float val = __uint_as_float(dr[j]);
            int cc = n0 + cb + c * 32 + j;
            if (MODE == 0) {
                if (cc >= 768 && cc < 1536) val += __ldg(extra + cc - 768);
            } else {
                val += __ldg(extra + cc);
            }
            v[j] = val;
        }
        if (MODE == 0) {
            uint16_t* dsth = Ch + (size_t)row * Nn + n0 + cb + c * 32;
            uint16_t* dstl = Cl + (size_t)row * Nn + n0 + cb + c * 32;
#pragma unroll
            for (int q4 = 0; q4 < 4; ++q4) {
                uint4 hv, lv;
                uint32_t* hw = (uint32_t*)&hv;
                uint32_t* lw = (uint32_t*)&lv;
#pragma unroll
                for (int j = 0; j < 4; ++j) {
                    float a = v[q4 * 8 + 2 * j], bb = v[q4 * 8 + 2 * j + 1];
                    uint32_t hvb = cvt2(a, bb);
                    hw[j] = hvb;
                    float la = a - __uint_as_float(hvb << 16);
                    float lb = bb - __uint_as_float(hvb & 0xffff0000u);
                    lw[j] = cvt2(la, lb);
                }
                *(uint4*)(dsth + q4 * 8) = hv;
                *(uint4*)(dstl + q4 * 8) = lv;
            }
        } else {
            float* dst = Cf + (size_t)row * Nn + n0 + cb + c * 32;
#pragma unroll
            for (int j4 = 0; j4 < 8; ++j4) {
                float4 o;
                o.x = v[j4 * 4 + 0]; o.y = v[j4 * 4 + 1];
                o.z = v[j4 * 4 + 2]; o.w = v[j4 * 4 + 3];
                *(float4*)(dst + j4 * 4) = o;
            }
        }
    }
    TC_FENCE_BEFORE();

    __syncthreads();
    if (wid == 0) {
        TC_DEALLOC(tmem, 128);
    }
#endif
}

// ===========================================================================
// tcgen05 attention, k-tile = 64, 2 CTAs/SM (97 KB smem). Unchanged (R15).
// ===========================================================================
__global__ __launch_bounds__(256, 2) void attn_mma(uint16_t* __restrict__ p16,
                                                   float* __restrict__ rsum)
{
#if HAS_TCGEN05
    extern __shared__ char smc[];
    const uint32_t base = smem_u32(smc);
    const uint32_t TMP = 0, MBQ = 8, MBP = 16, RS = 128;
    const uint32_t QHI = 1024,          QLO = QHI + 16384;   // [128 q][64 d]
    const uint32_t KHI = 33792,         KLO = KHI + 8192;    // [64 k][64 d]
    const uint32_t VTHI = 50176,        VTLO = VTHI + 8192;  // [64 d][64 k]
    const uint32_t PHI = 66560,         PLO = PHI + 16384;   // [128 q][64 k]

    const int tid = threadIdx.x;
    const int wid = tid >> 5;
    const int lane = tid & 31;
    const int bh = blockIdx.y;
    const int b  = bh / H_;
    const int h  = bh % H_;
    const int q0 = blockIdx.x * 128;

    if (wid == 0) {
        TC_ALLOC(base + TMP, 128);
        TC_RELINQ();
    }
    if (tid == 0) { MBAR_INIT(base + MBQ, 1); MBAR_INIT(base + MBP, 1); }
    __syncthreads();
    uint32_t tmem;
    asm volatile("ld.shared.b32 %0, [%1];" : "=r"(tmem) : "r"(base + TMP));
    const uint32_t S_ = tmem, O_ = tmem + 64;

    const size_t rowbase = (size_t)b * N_ * 2304;
    const uint16_t* qh = g_qkvh + rowbase + (size_t)q0 * 2304 + h * 64;
    const uint16_t* ql = g_qkvl + rowbase + (size_t)q0 * 2304 + h * 64;
    const uint16_t* kh = g_qkvh + rowbase + 768 + h * 64;
    const uint16_t* kl = g_qkvl + rowbase + 768 + h * 64;
    const uint16_t* vh = g_qkvh + rowbase + 1536 + h * 64;
    const uint16_t* vl = g_qkvl + rowbase + 1536 + h * 64;

    // Q fill: copy 128 rows x 64 bf16 per plane, swizzled
#pragma unroll
    for (int it = 0; it < 4; ++it) {
        int task = tid + it * 256;
        int r = task >> 3, g = task & 7;
        uint32_t dst = sw128((uint32_t)(r * 128 + g * 16));
        size_t off = (size_t)r * 2304 + g * 8;
        *(uint4*)(smc + QHI + dst) = *(const uint4*)(qh + off);
        *(uint4*)(smc + QLO + dst) = *(const uint4*)(ql + off);
    }

    const uint64_t dQhi = mk_desc(base + QHI), dQlo = mk_desc(base + QLO);
    const uint64_t dKhi = mk_desc(base + KHI), dKlo = mk_desc(base + KLO);
    const uint64_t dVh  = mk_desc(base + VTHI), dVl = mk_desc(base + VTLO);
    const uint64_t dPh  = mk_desc(base + PHI),  dPl = mk_desc(base + PLO);

    const int sub = wid & 3;
    const int row = sub * 32 + lane;            // q row within tile
    const int cb = (wid >> 2) * 32;             // k-col half for S epilogue
    float rs_acc = 0.f;

    // V-transpose mapping: 16 k-groups x 16 d-groups (4 rows x 4 d each)
    const int vk0 = (tid & 15) * 4;
    const int vd0 = (tid >> 4) * 4;

    for (int t = 0; t < 16; ++t) {
        // ---- K fill [64 k][64 d] (safe: QK(t-1) done via epi(t-1) MBQ wait) ----
#pragma unroll
        for (int it = 0; it < 2; ++it) {
            int task = tid + it * 256;
            int r = task >> 3, g = task & 7;
            uint32_t dst = sw128((uint32_t)(r * 128 + g * 16));
            size_t off = (size_t)(t * 64 + r) * 2304 + g * 8;
            *(uint4*)(smc + KHI + dst) = *(const uint4*)(kh + off);
            *(uint4*)(smc + KLO + dst) = *(const uint4*)(kl + off);
        }

        // ---- V loads + byte_perm into registers ----
        uint2 hvv[4], lvv[4];
#pragma unroll
        for (int i = 0; i < 4; ++i) {
            size_t off = (size_t)(t * 64 + vk0 + i) * 2304 + vd0;
            hvv[i] = *(const uint2*)(vh + off);
            lvv[i] = *(const uint2*)(vl + off);
        }
        uint2 voh[4], vol[4];
#pragma unroll
        for (int d = 0; d < 4; ++d) {
            uint32_t selw = (d & 1) ? 0x7632u : 0x5410u;
            uint32_t* hw = (uint32_t*)&voh[d];
            uint32_t* lw = (uint32_t*)&vol[d];
#pragma unroll
            for (int j = 0; j < 2; ++j) {
                uint32_t a = (d < 2) ? hvv[2 * j].x : hvv[2 * j].y;
                uint32_t c = (d < 2) ? hvv[2 * j + 1].x : hvv[2 * j + 1].y;
                hw[j] = __byte_perm(a, c, selw);
                uint32_t la = (d < 2) ? lvv[2 * j].x : lvv[2 * j].y;
                uint32_t lc = (d < 2) ? lvv[2 * j + 1].x : lvv[2 * j + 1].y;
                lw[j] = __byte_perm(la, lc, selw);
            }
        }
        // ---- PV(t-1) must be done before touching VT smem ----
        if (t > 0) MBAR_WAIT(base + MBP, (uint32_t)((t - 1) & 1));
#pragma unroll
        for (int d = 0; d < 4; ++d) {
            uint32_t off = sw128((uint32_t)((vd0 + d) * 128 + vk0 * 2));
            *(uint2*)(smc + VTHI + off) = voh[d];
            *(uint2*)(smc + VTLO + off) = vol[d];
        }
        __syncthreads();

        // ---- QK(t): S[128,64] ----
        if (wid == 0) {
            asm volatile("fence.proxy.async.shared::cta;" ::: "memory");
            if (elect_one()) {
#pragma unroll
                for (int ks = 0; ks < 4; ++ks) {
                    uint64_t o = (uint64_t)(ks * 2);
                    mma_f16_ss(S_, dQhi + o, dKhi + o, IDESC_N64, (uint32_t)(ks != 0));
                    mma_f16_ss(S_, dQhi + o, dKlo + o, IDESC_N64, 1u);
                    mma_f16_ss(S_, dQlo + o, dKhi + o, IDESC_N64, 1u);
                }
                TC_COMMIT(base + MBQ);
            }
        }
        MBAR_WAIT(base + MBQ, (uint32_t)(t & 1));
        TC_FENCE_AFTER();

        // ---- epilogue: LDTM S -> exp -> p16(gmem), rowsum, P -> smem ----
        {
            uint32_t sr[32];
            TC_LD_X32(sr, S_ + cb);
            TC_WAIT_LD();
            float p[32];
#pragma unroll
            for (int j = 0; j < 32; ++j) {
                p[j] = __expf(__uint_as_float(sr[j]) * SCALE_);
                rs_acc += p[j];
            }
            if (p16) {
                uint16_t* prow = p16 + ((size_t)bh * N_ + q0 + row) * N_
                               + t * 64 + cb;
                uint32_t pk[16];
#pragma unroll
                for (int j2 = 0; j2 < 16; ++j2) {
                    __half2 hh = __floats2half2_rn(p[2 * j2], p[2 * j2 + 1]);
                    pk[j2] = *(uint32_t*)&hh;
                }
#pragma unroll
                for (int u4 = 0; u4 < 4; ++u4)
                    *(uint4*)(prow + u4 * 8) = *(uint4*)(pk + u4 * 4);
            }
#pragma unroll
            for (int g = 0; g < 4; ++g) {
                uint4 hv4, lv4;
                uint32_t* hw = (uint32_t*)&hv4;
                uint32_t* lw = (uint32_t*)&lv4;
#pragma unroll
                for (int j = 0; j < 4; ++j) {
                    float a = p[8 * g + 2 * j], bb = p[8 * g + 2 * j + 1];
                    uint32_t hvb = cvt2(a, bb);
                    hw[j] = hvb;
                    float la = a - __uint_as_float(hvb << 16);
                    float lb = bb - __uint_as_float(hvb & 0xffff0000u);
                    lw[j] = cvt2(la, lb);
                }
                uint32_t off = sw128((uint32_t)(row * 128 + cb * 2 + g * 16));
                *(uint4*)(smc + PHI + off) = hv4;
                *(uint4*)(smc + PLO + off) = lv4;
            }
        }
        __syncthreads();

        // ---- PV: O += P @ (V^T)^T, M=128,N=64, 4 ksteps x 3 combos ----
        if (wid == 0) {
            asm volatile("fence.proxy.async.shared::cta;" ::: "memory");
            if (elect_one()) {
#pragma unroll
                for (int ks = 0; ks < 4; ++ks) {
                    uint64_t o = (uint64_t)(ks * 2);
                    mma_f16_ss(O_, dPh + o, dVh + o, IDESC_N64,
                               (uint32_t)((t | ks) != 0));
                    mma_f16_ss(O_, dPh + o, dVl + o, IDESC_N64, 1u);
                    mma_f16_ss(O_, dPl + o, dVh + o, IDESC_N64, 1u);
                }
                TC_COMMIT(base + MBP);
            }
        }
    }

    MBAR_WAIT(base + MBP, 1u);   // commit 16 -> parity (16-1)&1 = 1
    TC_FENCE_AFTER();

    // rowsum reduce across the two k-halves
    float* RSm = (float*)(smc + RS);
    if (wid < 4) RSm[row] = rs_acc;
    __syncthreads();
    if (wid >= 4) RSm[row] += rs_acc;
    __syncthreads();

    if (wid < 4) {
        float rsv = RSm[row];
        rsum[(size_t)bh * N_ + q0 + row] = rsv;
        float inv = 1.f / rsv;
        uint32_t orr[64];
        TC_LD_X32(orr, O_);
        TC_LD_X32(orr + 32, O_ + 32);
        TC_WAIT_LD();
        TC_FENCE_BEFORE();
        uint16_t* dsth = g_ah + ((size_t)b * N_ + q0 + row) * C_ + h * 64;
        uint16_t* dstl = g_al + ((size_t)b * N_ + q0 + row) * C_ + h * 64;
#pragma unroll
        for (int q4 = 0; q4 < 8; ++q4) {
            uint4 hv, lv;
            uint32_t* hw = (uint32_t*)&hv;
            uint32_t* lw = (uint32_t*)&lv;
#pragma unroll
            for (int j = 0; j < 4; ++j) {
                float a = __uint_as_float(orr[q4 * 8 + 2 * j]) * inv;
                float bb = __uint_as_float(orr[q4 * 8 + 2 * j + 1]) * inv;
                uint32_t hvb = cvt2(a, bb);
                hw[j] = hvb;
                float la = a - __uint_as_float(hvb << 16);
                float lb = bb - __uint_as_float(hvb & 0xffff0000u);
                lw[j] = cvt2(la, lb);
            }
            *(uint4*)(dsth + q4 * 8) = hv;
            *(uint4*)(dstl + q4 * 8) = lv;
        }
    }
    __syncthreads();
    if (wid == 0) TC_DEALLOC(tmem, 128);
#endif  // HAS_TCGEN05 (base-arch cubin never runs on GB300)
}

// ===========================================================================
// norm: probs_fp32 = fp16_unnormalized * (1/rsum). One block per row.
// ===========================================================================
__global__ __launch_bounds__(256) void norm_kernel(float* __restrict__ probs,
                                                   const uint16_t* __restrict__ p16,
                                                   const float* __restrict__ rsum)
{
    size_t row = blockIdx.x;
    float inv = 1.f / rsum[row];
    uint2 d = ((const uint2*)(p16 + row * N_))[threadIdx.x];
    __half2 h0 = *(__half2*)&d.x;
    __half2 h1 = *(__half2*)&d.y;
    float2 f0 = __half22float2(h0);
    float2 f1 = __half22float2(h1);
    float4 o;
    o.x = f0.x * inv; o.y = f0.y * inv;
    o.z = f1.x * inv; o.w = f1.y * inv;
    ((float4*)(probs + row * N_))[threadIdx.x] = o;
}

// ===========================================================================
extern "C" void kernel_launch(void* const* d_in, const int* in_sizes, int n_in,
                              void* d_out, int out_size)
{
    const float* x     = (const float*)d_in[0];
    const float* se    = (const float*)d_in[1];
    const float* wqkv  = (const float*)d_in[2];
    const float* wproj = (const float*)d_in[3];
    const float* bproj = (const float*)d_in[4];

    float* out = (float*)d_out;
    const long long OUTN = (long long)B_ * N_ * C_;
    const long long PRN  = (long long)B_ * H_ * N_ * N_;

    float* probs = nullptr;
    bool do_proj = true;
    if ((long long)out_size >= OUTN + PRN) {
        probs = out + OUTN;
    } else if ((long long)out_size == PRN) {
        probs = out;
        do_proj = false;
    }

    uint16_t *xh, *xl, *wqh, *wql, *wph, *wpl, *qkvh, *qkvl, *ah, *al, *p16;
    float* rsum;
    cudaGetSymbolAddress((void**)&xh, g_xh);
    cudaGetSymbolAddress((void**)&xl, g_xl);
    cudaGetSymbolAddress((void**)&wqh, g_wqh);
    cudaGetSymbolAddress((void**)&wql, g_wql);
    cudaGetSymbolAddress((void**)&wph, g_wph);
    cudaGetSymbolAddress((void**)&wpl, g_wpl);
    cudaGetSymbolAddress((void**)&qkvh, g_qkvh);
    cudaGetSymbolAddress((void**)&qkvl, g_qkvl);
    cudaGetSymbolAddress((void**)&ah, g_ah);
    cudaGetSymbolAddress((void**)&al, g_al);
    cudaGetSymbolAddress((void**)&p16, g_p16);
    cudaGetSymbolAddress((void**)&rsum, g_rsum);

    const int GEMM_SMEM = 1024 + 4 * 16384;      // 66560 -> 3 CTAs/SM
    const int ATTN_SMEM = 99328;                 // 97 KB  -> 2 CTAs/SM
    static int smem_set = 0;
    if (!smem_set) {
        cudaFuncSetAttribute(mma_gemm<0>,
                             cudaFuncAttributeMaxDynamicSharedMemorySize, GEMM_SMEM);
        cudaFuncSetAttribute(mma_gemm<1>,
                             cudaFuncAttributeMaxDynamicSharedMemorySize, GEMM_SMEM);
        cudaFuncSetAttribute(attn_mma,
                             cudaFuncAttributeMaxDynamicSharedMemorySize, ATTN_SMEM);
        smem_set = 1;
    }

    // 0) prep: fp32 -> bf16 hi/lo planes
    {
        int nx = B_ * N_ * C_ / 8;          // 786432
        int nq = 3 * C_ * C_ / 8;           // 221184
        int np = C_ * C_ / 8;               // 73728
        prep_kernel<<<(nx + 255) / 256, 256>>>(x, xh, xl, nx);
        prep_kernel<<<(nq + 255) / 256, 256>>>(wqkv, wqh, wql, nq);
        prep_kernel<<<(np + 255) / 256, 256>>>(wproj, wph, wpl, np);
    }
    // 1) qkv = x @ w_qkv^T (+scale_emb on K slice) -> hi/lo planes
    {
        dim3 grid(3 * C_ / 128, (B_ * N_) / 128);   // (18, 64)
        mma_gemm<0><<<grid, 256, GEMM_SMEM>>>(xh, xl, wqh, wql,
                                              nullptr, qkvh, qkvl,
                                              3 * C_, C_, se);
    }
    // 2) tcgen05 attention (fp16 unnormalized probs + rowsums)
    {
        dim3 grid(N_ / 128, B_ * H_);               // (8, 96)
        attn_mma<<<grid, 256, ATTN_SMEM>>>(probs ? p16 : nullptr, rsum);
    }
    // 2b) normalize probs: fp16 -> fp32
    if (probs) {
        norm_kernel<<<B_ * H_ * N_, 256>>>(probs, p16, rsum);
    }
    // 3) out = attn @ w_proj^T + b_proj (fp32 output)
    if (do_proj) {
        dim3 grid(C_ / 128, (B_ * N_) / 128);       // (6, 64)
        mma_gemm<1><<<grid, 256, GEMM_SMEM>>>(ah, al, wph, wpl,
                                              out, nullptr, nullptr,
                                              C_, C_, bproj);
    }
}

// round 17
// speedup vs baseline: 1.0398x; 1.0398x over previous
#include <cuda_runtime.h>
#include <cuda_bf16.h>
#include <cuda_fp16.h>
#include <math_constants.h>
#include <cstdint>

#define B_  8
#define N_  1024
#define C_  768
#define H_  12
#define D_  64
#define SCALE_ 0.125f

// Scratch (device globals: no allocation allowed). Inter-kernel tensors are
// bf16 hi/lo plane pairs (hi = rn(x), lo = rn(x - hi)).
__device__ uint16_t g_xh[(size_t)B_ * N_ * C_],      g_xl[(size_t)B_ * N_ * C_];
__device__ uint16_t g_wqh[(size_t)3 * C_ * C_],      g_wql[(size_t)3 * C_ * C_];
__device__ uint16_t g_wph[(size_t)C_ * C_],          g_wpl[(size_t)C_ * C_];
__device__ uint16_t g_qkvh[(size_t)B_ * N_ * 3 * C_], g_qkvl[(size_t)B_ * N_ * 3 * C_];
__device__ uint16_t g_ah[(size_t)B_ * N_ * C_],      g_al[(size_t)B_ * N_ * C_];
__device__ uint16_t g_p16[(size_t)B_ * H_ * N_ * N_];   // unnormalized probs, fp16
__device__ float    g_rsum[(size_t)B_ * H_ * N_];

// Feature gate: tcgen05 only exists in the sm_103a/sm_100a-specific cubin.
#if defined(__CUDA_ARCH_FEAT_SM103_ALL) || defined(__CUDA_ARCH_FEAT_SM100_ALL)
#define HAS_TCGEN05 1
#else
#define HAS_TCGEN05 0
#endif

// ===========================================================================
// prep: fp32 -> bf16 hi/lo planes. 8 elems per thread.
// ===========================================================================
__global__ __launch_bounds__(256) void prep_kernel(
    const float* __restrict__ src, uint16_t* __restrict__ hi,
    uint16_t* __restrict__ lo, int n8)
{
    int i = blockIdx.x * blockDim.x + threadIdx.x;
    if (i >= n8) return;
    float v[8];
    *(float4*)(v)     = ((const float4*)src)[2 * i];
    *(float4*)(v + 4) = ((const float4*)src)[2 * i + 1];
    uint16_t hv[8], lv[8];
#pragma unroll
    for (int j = 0; j < 8; ++j) {
        __nv_bfloat16 h = __float2bfloat16_rn(v[j]);
        hv[j] = *(uint16_t*)&h;
        __nv_bfloat16 l = __float2bfloat16_rn(v[j] - __bfloat162float(h));
        lv[j] = *(uint16_t*)&l;
    }
    ((uint4*)hi)[i] = *(uint4*)hv;
    ((uint4*)lo)[i] = *(uint4*)lv;
}

#if HAS_TCGEN05
// ===========================================================================
// PTX helpers (verified encodings only)
// ===========================================================================
__device__ __forceinline__ uint32_t smem_u32(const void* p) {
    uint32_t a;
    asm("{ .reg .u64 t; cvta.to.shared.u64 t, %1; cvt.u32.u64 %0, t; }"
        : "=r"(a) : "l"(p));
    return a;
}
__device__ __forceinline__ uint32_t elect_one() {
    uint32_t pred;
    asm volatile("{\n\t.reg .pred p;\n\telect.sync _|p, 0xFFFFFFFF;\n\t"
                 "selp.b32 %0, 1, 0, p;\n\t}" : "=r"(pred));
    return pred;
}
#define TC_ALLOC(sm_addr, n) \
    asm volatile("tcgen05.alloc.cta_group::1.sync.aligned.shared::cta.b32 [%0], %1;" \
                 :: "r"(sm_addr), "r"((uint32_t)(n)) : "memory")
#define TC_DEALLOC(tm, n) \
    asm volatile("tcgen05.dealloc.cta_group::1.sync.aligned.b32 %0, %1;" \
                 :: "r"(tm), "r"((uint32_t)(n)))
#define TC_RELINQ() \
    asm volatile("tcgen05.relinquish_alloc_permit.cta_group::1.sync.aligned;")
#define TC_COMMIT(mbar) \
    asm volatile("tcgen05.commit.cta_group::1.mbarrier::arrive::one.shared::cluster.b64 [%0];" \
                 :: "r"(mbar) : "memory")
#define TC_FENCE_AFTER()  asm volatile("tcgen05.fence::after_thread_sync;" ::: "memory")
#define TC_FENCE_BEFORE() asm volatile("tcgen05.fence::before_thread_sync;" ::: "memory")
#define TC_WAIT_LD() asm volatile("tcgen05.wait::ld.sync.aligned;" ::: "memory")
#define MBAR_INIT(a, c) \
    asm volatile("mbarrier.init.shared.b64 [%0], %1;" :: "r"(a), "r"((uint32_t)(c)) : "memory")
#define MBAR_WAIT(a, ph) do {                                                   \
    uint32_t _m = (a), _p = (ph), _d;                                           \
    asm volatile("{\n\t.reg .pred p;\n\t"                                       \
        "mbarrier.try_wait.parity.acquire.cta.shared::cta.b64 p, [%1], %2;\n\t" \
        "selp.b32 %0, 1, 0, p;\n\t}" : "=r"(_d) : "r"(_m), "r"(_p) : "memory"); \
    if (!_d) {                                                                   \
        asm volatile("{\n\t.reg .pred P1;\n\t"                                   \
            "W%=:\n\t"                                                           \
            "mbarrier.try_wait.parity.acquire.cta.shared::cta.b64 P1, [%0], %1, 0x989680;\n\t" \
            "@P1 bra.uni D%=;\n\t"                                               \
            "bra.uni W%=;\n\t"                                                   \
            "D%=:\n\t}" :: "r"(_m), "r"(_p) : "memory");                         \
    } } while (0)
#define TC_LD_X32(r, tm) \
    asm volatile("tcgen05.ld.sync.aligned.32x32b.x32.b32 " \
        "{%0, %1, %2, %3, %4, %5, %6, %7, %8, %9, %10, %11, %12, %13, %14, %15, " \
        " %16, %17, %18, %19, %20, %21, %22, %23, %24, %25, %26, %27, %28, %29, %30, %31}, [%32];" \
        : "=r"((r)[0]),  "=r"((r)[1]),  "=r"((r)[2]),  "=r"((r)[3]),  \
          "=r"((r)[4]),  "=r"((r)[5]),  "=r"((r)[6]),  "=r"((r)[7]),  \
          "=r"((r)[8]),  "=r"((r)[9]),  "=r"((r)[10]), "=r"((r)[11]), \
          "=r"((r)[12]), "=r"((r)[13]), "=r"((r)[14]), "=r"((r)[15]), \
          "=r"((r)[16]), "=r"((r)[17]), "=r"((r)[18]), "=r"((r)[19]), \
          "=r"((r)[20]), "=r"((r)[21]), "=r"((r)[22]), "=r"((r)[23]), \
          "=r"((r)[24]), "=r"((r)[25]), "=r"((r)[26]), "=r"((r)[27]), \
          "=r"((r)[28]), "=r"((r)[29]), "=r"((r)[30]), "=r"((r)[31]) \
        : "r"(tm))

static constexpr uint64_t DESC_SW128 =
    (uint64_t(2) << 61) | (uint64_t(1) << 46) | (uint64_t(64) << 32) | (uint64_t(1) << 16);
__device__ __forceinline__ uint64_t mk_desc(uint32_t addr) {
    return DESC_SW128 | ((uint64_t)(addr >> 4) & 0x3FFF);
}
__device__ __forceinline__ uint32_t sw128(uint32_t off) {
    return off ^ ((off >> 3) & 0x70);
}
// cvt2(a,b): lo half = a, hi half = b
__device__ __forceinline__ uint32_t cvt2(float a, float b) {
    uint32_t d;
    asm("cvt.rn.bf16x2.f32 %0, %1, %2;" : "=r"(d) : "f"(b), "f"(a));
    return d;
}
// SS-mode f16-kind MMA (bf16 or fp16 per idesc type fields)
__device__ __forceinline__ void mma_f16_ss(uint32_t d, uint64_t ad, uint64_t bd,
                                           uint32_t idesc, uint32_t en) {
    asm volatile(
        "{\n\t.reg .pred p;\n\t"
        "setp.ne.u32 p, %5, 0;\n\t"
        "tcgen05.mma.cta_group::1.kind::f16 [%0], %1, %2, %3, {%4, %4, %4, %4}, p;\n\t}"
        :: "r"(d), "l"(ad), "l"(bd), "r"(idesc), "r"(0u), "r"(en) : "memory");
}

static constexpr uint32_t IDESC_128 =
    (1u << 4) | (1u << 7) | (1u << 10) | (16u << 17) | (8u << 24);   // bf16 M=128,N=128
static constexpr uint32_t IDESC_N64 =
    (1u << 4) | (1u << 7) | (1u << 10) | (8u << 17) | (8u << 24);    // bf16 M=128,N=64
static constexpr uint32_t IDESC_N64_F16 =
    (1u << 4) | (8u << 17) | (8u << 24);                              // fp16 M=128,N=64
#endif  // HAS_TCGEN05

// ===========================================================================
// GEMM on bf16 planes, single-buffered, 2 CTAs/SM (reverted to R15 config).
// MODE 0 (qkv): +scale_emb on cols [768,1536), writes hi/lo planes.
// MODE 1 (proj): +bias, writes fp32.
// ===========================================================================
template <int MODE>
__global__ __launch_bounds__(256, 2) void mma_gemm(
    const uint16_t* __restrict__ Ah, const uint16_t* __restrict__ Al,
    const uint16_t* __restrict__ Wh, const uint16_t* __restrict__ Wl,
    float* __restrict__ Cf, uint16_t* __restrict__ Ch, uint16_t* __restrict__ Cl,
    int Nn, int K, const float* __restrict__ extra)
{
#if HAS_TCGEN05
    extern __shared__ char smc[];
    const uint32_t smem_base = smem_u32(smc);
    const uint32_t TMP = 0, MB = 8;
    const uint32_t BUF = 1024;   // AHI +0, ALO +16K, WHI +32K, WLO +48K

    const int tid = threadIdx.x;
    const int wid = tid >> 5;
    const int m0 = blockIdx.y * 128;
    const int n0 = blockIdx.x * 128;

    if (wid == 0) {
        TC_ALLOC(smem_base + TMP, 128);
        TC_RELINQ();
    }
    if (tid == 0) MBAR_INIT(smem_base + MB, 1);
    __syncthreads();
    uint32_t tmem;
    asm volatile("ld.shared.b32 %0, [%1];" : "=r"(tmem) : "r"(smem_base + TMP));

    const uint64_t dAhi = mk_desc(smem_base + BUF);
    const uint64_t dAlo = mk_desc(smem_base + BUF + 16384);
    const uint64_t dWhi = mk_desc(smem_base + BUF + 32768);
    const uint64_t dWlo = mk_desc(smem_base + BUF + 49152);

    const int nch = K / 64;
    for (int ch = 0; ch < nch; ++ch) {
        const int kt = ch * 64;
#pragma unroll
        for (int it = 0; it < 4; ++it) {
            int task = tid + it * 256;
            int r = task >> 3, g = task & 7;
            uint32_t dst = sw128((uint32_t)(r * 128 + g * 16));
            size_t aoff = (size_t)(m0 + r) * K + kt + g * 8;
            size_t woff = (size_t)(n0 + r) * K + kt + g * 8;
            *(uint4*)(smc + BUF + dst)         = *(const uint4*)(Ah + aoff);
            *(uint4*)(smc + BUF + 16384 + dst) = *(const uint4*)(Al + aoff);
            *(uint4*)(smc + BUF + 32768 + dst) = *(const uint4*)(Wh + woff);
            *(uint4*)(smc + BUF + 49152 + dst) = *(const uint4*)(Wl + woff);
        }
        __syncthreads();

        if (wid == 0) {
            asm volatile("fence.proxy.async.shared::cta;" ::: "memory");
            if (elect_one()) {
#pragma unroll
                for (int ks = 0; ks < 4; ++ks) {
                    uint64_t o = (uint64_t)(ks * 2);
                    mma_f16_ss(tmem, dAhi + o, dWhi + o, IDESC_128,
                               (uint32_t)((ch | ks) != 0));
                    mma_f16_ss(tmem, dAhi + o, dWlo + o, IDESC_128, 1u);
                    mma_f16_ss(tmem, dAlo + o, dWhi + o, IDESC_128, 1u);
                }
                TC_COMMIT(smem_base + MB);
            }
        }
        MBAR_WAIT(smem_base + MB, (uint32_t)(ch & 1));
    }
    TC_FENCE_AFTER();

    const int lane = tid & 31;
    const int sub = wid & 3;
    const int cb = (wid >> 2) * 64;
    const int row = m0 + sub * 32 + lane;

#pragma unroll
    for (int c = 0; c < 2; ++c) {
        uint32_t dr[32];
        TC_LD_X32(dr, tmem + cb + c * 32);
        TC_WAIT_LD();
        float v[32];
#pragma unroll
        for (int j = 0; j < 32; ++j) {
            float val = __uint_as_float(dr[j]);
            int cc = n0 + cb + c * 32 + j;
            if (MODE == 0) {
                if (cc >= 768 && cc < 1536) val += __ldg(extra + cc - 768);
            } else {
                val += __ldg(extra + cc);
            }
            v[j] = val;
        }
        if (MODE == 0) {
            uint16_t* dsth = Ch + (size_t)row * Nn + n0 + cb + c * 32;
            uint16_t* dstl = Cl + (size_t)row * Nn + n0 + cb + c * 32;
#pragma unroll
            for (int q4 = 0; q4 < 4; ++q4) {
                uint4 hv, lv;
                uint32_t* hw = (uint32_t*)&hv;
                uint32_t* lw = (uint32_t*)&lv;
#pragma unroll
                for (int j = 0; j < 4; ++j) {
                    float a = v[q4 * 8 + 2 * j], bb = v[q4 * 8 + 2 * j + 1];
                    uint32_t hvb = cvt2(a, bb);
                    hw[j] = hvb;
                    float la = a - __uint_as_float(hvb << 16);
                    float lb = bb - __uint_as_float(hvb & 0xffff0000u);
                    lw[j] = cvt2(la, lb);
                }
                *(uint4*)(dsth + q4 * 8) = hv;
                *(uint4*)(dstl + q4 * 8) = lv;
            }
        } else {
            float* dst = Cf + (size_t)row * Nn + n0 + cb + c * 32;
#pragma unroll
            for (int j4 = 0; j4 < 8; ++j4) {
                float4 o;
                o.x = v[j4 * 4 + 0]; o.y = v[j4 * 4 + 1];
                o.z = v[j4 * 4 + 2]; o.w = v[j4 * 4 + 3];
                *(float4*)(dst + j4 * 4) = o;
            }
        }
    }
    TC_FENCE_BEFORE();

    __syncthreads();
    if (wid == 0) {
        TC_DEALLOC(tmem, 128);
    }
#endif
}

// ===========================================================================
// tcgen05 attention, k-tile 64, fp16 PV, 3 CTAs/SM (73 KB smem).
// QK: bf16 hi/lo (3 combos). PV: fp16 single planes (1 combo, 4 dispatches).
// P fp16 = same values as the probs output conversion (reused).
// ===========================================================================
__global__ __launch_bounds__(256, 3) void attn_mma(uint16_t* __restrict__ p16,
                                                   float* __restrict__ rsum)
{
#if HAS_TCGEN05
    extern __shared__ char smc[];
    const uint32_t base = smem_u32(smc);
    const uint32_t TMP = 0, MBQ = 8, MBP = 16, RS = 128;   // RS: 128 floats
    const uint32_t QHI = 1024,   QLO = 17408;    // [128 q][64 d] bf16
    const uint32_t KHI = 33792,  KLO = 41984;    // [64 k][64 d] bf16
    const uint32_t VTF = 50176;                  // [64 d][64 k] fp16 (8 KB)
    const uint32_t PF  = 58368;                  // [128 q][64 k] fp16 (16 KB)
    // total = 58368 + 16384 = 74752 bytes -> 3 CTAs/SM

    const int tid = threadIdx.x;
    const int wid = tid >> 5;
    const int lane = tid & 31;
    const int bh = blockIdx.y;
    const int b  = bh / H_;
    const int h  = bh % H_;
    const int q0 = blockIdx.x * 128;

    if (wid == 0) {
        TC_ALLOC(base + TMP, 128);
        TC_RELINQ();
    }
    if (tid == 0) { MBAR_INIT(base + MBQ, 1); MBAR_INIT(base + MBP, 1); }
    __syncthreads();
    uint32_t tmem;
    asm volatile("ld.shared.b32 %0, [%1];" : "=r"(tmem) : "r"(base + TMP));
    const uint32_t S_ = tmem, O_ = tmem + 64;

    const size_t rowbase = (size_t)b * N_ * 2304;
    const uint16_t* qh = g_qkvh + rowbase + (size_t)q0 * 2304 + h * 64;
    const uint16_t* ql = g_qkvl + rowbase + (size_t)q0 * 2304 + h * 64;
    const uint16_t* kh = g_qkvh + rowbase + 768 + h * 64;
    const uint16_t* kl = g_qkvl + rowbase + 768 + h * 64;
    const uint16_t* vh = g_qkvh + rowbase + 1536 + h * 64;
    const uint16_t* vl = g_qkvl + rowbase + 1536 + h * 64;

    // Q fill: copy 128 rows x 64 bf16 per plane, swizzled
#pragma unroll
    for (int it = 0; it < 4; ++it) {
        int task = tid + it * 256;
        int r = task >> 3, g = task & 7;
        uint32_t dst = sw128((uint32_t)(r * 128 + g * 16));
        size_t off = (size_t)r * 2304 + g * 8;
        *(uint4*)(smc + QHI + dst) = *(const uint4*)(qh + off);
        *(uint4*)(smc + QLO + dst) = *(const uint4*)(ql + off);
    }

    const uint64_t dQhi = mk_desc(base + QHI), dQlo = mk_desc(base + QLO);
    const uint64_t dKhi = mk_desc(base + KHI), dKlo = mk_desc(base + KLO);
    const uint64_t dVt  = mk_desc(base + VTF), dPf = mk_desc(base + PF);

    const int sub = wid & 3;
    const int row = sub * 32 + lane;            // q row within tile
    const int cb = (wid >> 2) * 32;             // k-col half for S epilogue
    float rs_acc = 0.f;

    // V-transpose mapping: (tid&15) -> 4 k rows, (tid>>4) -> 4 d cols
    const int vk0 = (tid & 15) * 4;
    const int vd0 = (tid >> 4) * 4;

    for (int t = 0; t < 16; ++t) {
        // ---- K fill [64 k][64 d] (safe: QK(t-1) done via epi(t-1) MBQ wait) ----
#pragma unroll
        for (int it = 0; it < 2; ++it) {
            int task = tid + it * 256;
            int r = task >> 3, g = task & 7;
            uint32_t dst = sw128((uint32_t)(r * 128 + g * 16));
            size_t off = (size_t)(t * 64 + r) * 2304 + g * 8;
            *(uint4*)(smc + KHI + dst) = *(const uint4*)(kh + off);
            *(uint4*)(smc + KLO + dst) = *(const uint4*)(kl + off);
        }

        // ---- V: load bf16 hi/lo, reconstruct fp32, pack fp16, transpose ----
        uint2 hvv[4], lvv[4];
#pragma unroll
        for (int i = 0; i < 4; ++i) {
            size_t off = (size_t)(t * 64 + vk0 + i) * 2304 + vd0;
            hvv[i] = *(const uint2*)(vh + off);
            lvv[i] = *(const uint2*)(vl + off);
        }
        float vf[4][4];
#pragma unroll
        for (int i = 0; i < 4; ++i) {
            vf[i][0] = __uint_as_float(hvv[i].x << 16)
                     + __uint_as_float(lvv[i].x << 16);
            vf[i][1] = __uint_as_float(hvv[i].x & 0xffff0000u)
                     + __uint_as_float(lvv[i].x & 0xffff0000u);
            vf[i][2] = __uint_as_float(hvv[i].y << 16)
                     + __uint_as_float(lvv[i].y << 16);
            vf[i][3] = __uint_as_float(hvv[i].y & 0xffff0000u)
                     + __uint_as_float(lvv[i].y & 0xffff0000u);
        }
        uint2 vo[4];
#pragma unroll
        for (int d = 0; d < 4; ++d) {
            __half2 h0 = __floats2half2_rn(vf[0][d], vf[1][d]);
            __half2 h1 = __floats2half2_rn(vf[2][d], vf[3][d]);
            vo[d].x = *(uint32_t*)&h0;
            vo[d].y = *(uint32_t*)&h1;
        }
        // ---- PV(t-1) must be done before touching VT smem ----
        if (t > 0) MBAR_WAIT(base + MBP, (uint32_t)((t - 1) & 1));
#pragma unroll
        for (int d = 0; d < 4; ++d) {
            uint32_t off = sw128((uint32_t)((vd0 + d) * 128 + vk0 * 2));
            *(uint2*)(smc + VTF + off) = vo[d];
        }
        __syncthreads();

        // ---- QK(t): S[128,64], bf16 hi/lo ----
        if (wid == 0) {
            asm volatile("fence.proxy.async.shared::cta;" ::: "memory");
            if (elect_one()) {
#pragma unroll
                for (int ks = 0; ks < 4; ++ks) {
                    uint64_t o = (uint64_t)(ks * 2);
                    mma_f16_ss(S_, dQhi + o, dKhi + o, IDESC_N64, (uint32_t)(ks != 0));
                    mma_f16_ss(S_, dQhi + o, dKlo + o, IDESC_N64, 1u);
                    mma_f16_ss(S_, dQlo + o, dKhi + o, IDESC_N64, 1u);
                }
                TC_COMMIT(base + MBQ);
            }
        }
        MBAR_WAIT(base + MBQ, (uint32_t)(t & 1));
        TC_FENCE_AFTER();

        // ---- epilogue: LDTM S -> exp -> fp16 pk -> p16(gmem) + P(smem) ----
        {
            uint32_t sr[32];
            TC_LD_X32(sr, S_ + cb);
            TC_WAIT_LD();
            float p[32];
#pragma unroll
            for (int j = 0; j < 32; ++j) {
                p[j] = __expf(__uint_as_float(sr[j]) * SCALE_);
                rs_acc += p[j];
            }
            uint32_t pk[16];
#pragma unroll
            for (int j2 = 0; j2 < 16; ++j2) {
                __half2 hh = __floats2half2_rn(p[2 * j2], p[2 * j2 + 1]);
                pk[j2] = *(uint32_t*)&hh;
            }
            if (p16) {
                uint16_t* prow = p16 + ((size_t)bh * N_ + q0 + row) * N_
                               + t * 64 + cb;
#pragma unroll
                for (int u4 = 0; u4 < 4; ++u4)
                    *(uint4*)(prow + u4 * 8) = *(uint4*)(pk + u4 * 4);
            }
            // store P fp16 to smem (same pk values)
#pragma unroll
            for (int g = 0; g < 4; ++g) {
                uint32_t off = sw128((uint32_t)(row * 128 + cb * 2 + g * 16));
                *(uint4*)(smc + PF + off) = *(uint4*)(pk + g * 4);
            }
        }
        __syncthreads();

        // ---- PV: O += P @ (V^T)^T, fp16, 4 ksteps ----
        if (wid == 0) {
            asm volatile("fence.proxy.async.shared::cta;" ::: "memory");
            if (elect_one()) {
#pragma unroll
                for (int ks = 0; ks < 4; ++ks) {
                    uint64_t o = (uint64_t)(ks * 2);
                    mma_f16_ss(O_, dPf + o, dVt + o, IDESC_N64_F16,
                               (uint32_t)((t | ks) != 0));
                }
                TC_COMMIT(base + MBP);
            }
        }
    }

    MBAR_WAIT(base + MBP, 1u);   // commit 16 -> last parity 1
    TC_FENCE_AFTER();

    // rowsum reduce across the two k-halves
    float* RSm = (float*)(smc + RS);
    if (wid < 4) RSm[row] = rs_acc;
    __syncthreads();
    if (wid >= 4) RSm[row] += rs_acc;
    __syncthreads();

    if (wid < 4) {
        float rsv = RSm[row];
        rsum[(size_t)bh * N_ + q0 + row] = rsv;
        float inv = 1.f / rsv;
        uint32_t orr[64];
        TC_LD_X32(orr, O_);
        TC_LD_X32(orr + 32, O_ + 32);
        TC_WAIT_LD();
        TC_FENCE_BEFORE();
        uint16_t* dsth = g_ah + ((size_t)b * N_ + q0 + row) * C_ + h * 64;
        uint16_t* dstl = g_al + ((size_t)b * N_ + q0 + row) * C_ + h * 64;
#pragma unroll
        for (int q4 = 0; q4 < 8; ++q4) {
            uint4 hv, lv;
            uint32_t* hw = (uint32_t*)&hv;
            uint32_t* lw = (uint32_t*)&lv;
#pragma unroll
            for (int j = 0; j < 4; ++j) {
                float a = __uint_as_float(orr[q4 * 8 + 2 * j]) * inv;
                float bb = __uint_as_float(orr[q4 * 8 + 2 * j + 1]) * inv;
                uint32_t hvb = cvt2(a, bb);
                hw[j] = hvb;
                float la = a - __uint_as_float(hvb << 16);
                float lb = bb - __uint_as_float(hvb & 0xffff0000u);
                lw[j] = cvt2(la, lb);
            }
            *(uint4*)(dsth + q4 * 8) = hv;
            *(uint4*)(dstl + q4 * 8) = lv;
        }
    }
    __syncthreads();
    if (wid == 0) TC_DEALLOC(tmem, 128);
#endif  // HAS_TCGEN05 (base-arch cubin never runs on GB300)
}

// ===========================================================================
// norm: probs_fp32 = fp16_unnormalized * (1/rsum). One block per row.
// ===========================================================================
__global__ __launch_bounds__(256) void norm_kernel(float* __restrict__ probs,
                                                   const uint16_t* __restrict__ p16,
                                                   const float* __restrict__ rsum)
{
    size_t row = blockIdx.x;
    float inv = 1.f / rsum[row];
    uint2 d = ((const uint2*)(p16 + row * N_))[threadIdx.x];
    __half2 h0 = *(__half2*)&d.x;
    __half2 h1 = *(__half2*)&d.y;
    float2 f0 = __half22float2(h0);
    float2 f1 = __half22float2(h1);
    float4 o;
    o.x = f0.x * inv; o.y = f0.y * inv;
    o.z = f1.x * inv; o.w = f1.y * inv;
    ((float4*)(probs + row * N_))[threadIdx.x] = o;
}

// ===========================================================================
extern "C" void kernel_launch(void* const* d_in, const int* in_sizes, int n_in,
                              void* d_out, int out_size)
{
    const float* x     = (const float*)d_in[0];
    const float* se    = (const float*)d_in[1];
    const float* wqkv  = (const float*)d_in[2];
    const float* wproj = (const float*)d_in[3];
    const float* bproj = (const float*)d_in[4];

    float* out = (float*)d_out;
    const long long OUTN = (long long)B_ * N_ * C_;
    const long long PRN  = (long long)B_ * H_ * N_ * N_;

    float* probs = nullptr;
    bool do_proj = true;
    if ((long long)out_size >= OUTN + PRN) {
        probs = out + OUTN;
    } else if ((long long)out_size == PRN) {
        probs = out;
        do_proj = false;
    }

    uint16_t *xh, *xl, *wqh, *wql, *wph, *wpl, *qkvh, *qkvl, *ah, *al, *p16;
    float* rsum;
    cudaGetSymbolAddress((void**)&xh, g_xh);
    cudaGetSymbolAddress((void**)&xl, g_xl);
    cudaGetSymbolAddress((void**)&wqh, g_wqh);
    cudaGetSymbolAddress((void**)&wql, g_wql);
    cudaGetSymbolAddress((void**)&wph, g_wph);
    cudaGetSymbolAddress((void**)&wpl, g_wpl);
    cudaGetSymbolAddress((void**)&qkvh, g_qkvh);
    cudaGetSymbolAddress((void**)&qkvl, g_qkvl);
    cudaGetSymbolAddress((void**)&ah, g_ah);
    cudaGetSymbolAddress((void**)&al, g_al);
    cudaGetSymbolAddress((void**)&p16, g_p16);
    cudaGetSymbolAddress((void**)&rsum, g_rsum);

    const int GEMM_SMEM = 1024 + 4 * 16384;      // 66560 -> 2 CTAs/SM
    const int ATTN_SMEM = 74752;                 // 73 KB  -> 3 CTAs/SM
    static int smem_set = 0;
    if (!smem_set) {
        cudaFuncSetAttribute(mma_gemm<0>,
                             cudaFuncAttributeMaxDynamicSharedMemorySize, GEMM_SMEM);
        cudaFuncSetAttribute(mma_gemm<1>,
                             cudaFuncAttributeMaxDynamicSharedMemorySize, GEMM_SMEM);
        cudaFuncSetAttribute(attn_mma,
                             cudaFuncAttributeMaxDynamicSharedMemorySize, ATTN_SMEM);
        smem_set = 1;
    }

    // 0) prep: fp32 -> bf16 hi/lo planes
    {
        int nx = B_ * N_ * C_ / 8;          // 786432
        int nq = 3 * C_ * C_ / 8;           // 221184
        int np = C_ * C_ / 8;               // 73728
        prep_kernel<<<(nx + 255) / 256, 256>>>(x, xh, xl, nx);
        prep_kernel<<<(nq + 255) / 256, 256>>>(wqkv, wqh, wql, nq);
        prep_kernel<<<(np + 255) / 256, 256>>>(wproj, wph, wpl, np);
    }
    // 1) qkv = x @ w_qkv^T (+scale_emb on K slice) -> hi/lo planes
    {
        dim3 grid(3 * C_ / 128, (B_ * N_) / 128);   // (18, 64)
        mma_gemm<0><<<grid, 256, GEMM_SMEM>>>(xh, xl, wqh, wql,
                                              nullptr, qkvh, qkvl,
                                              3 * C_, C_, se);
    }
    // 2) tcgen05 attention (fp16 unnormalized probs + rowsums)
    {
        dim3 grid(N_ / 128, B_ * H_);               // (8, 96)
        attn_mma<<<grid, 256, ATTN_SMEM>>>(probs ? p16 : nullptr, rsum);
    }
    // 2b) normalize probs: fp16 -> fp32
    if (probs) {
        norm_kernel<<<B_ * H_ * N_, 256>>>(probs, p16, rsum);
    }
    // 3) out = attn @ w_proj^T + b_proj (fp32 output)
    if (do_proj) {
        dim3 grid(C_ / 128, (B_ * N_) / 128);       // (6, 64)
        mma_gemm<1><<<grid, 256, GEMM_SMEM>>>(ah, al, wph, wpl,
                                              out, nullptr, nullptr,
                                              C_, C_, bproj);
    }
}